// round 4
// baseline (speedup 1.0000x reference)
#include <cuda_runtime.h>
#include <cuda_bf16.h>
#include <cstddef>
#include <math.h>

// Problem constants
#define BB 4
#define LSEQ 2048
#define DMODEL 1024
#define NH 16
#define HDIM 64
#define MROWS (BB * LSEQ)      // 8192
#define QKVN (3 * DMODEL)      // 3072

// Scratch (static device arrays; no allocation APIs allowed)
__device__ float g_qkv[(size_t)MROWS * QKVN];    // (B*L, 3D)
__device__ float g_attn[(size_t)MROWS * DMODEL]; // (B*L, D) attention output

// ---------------------------------------------------------------------------
// Tiled fp32 GEMM: C[M,N] = A[M,K] @ B[K,N] (+bias). BM=BN=128, BK=16,
// 256 threads, 8x8 per-thread microtile.
// ---------------------------------------------------------------------------
#define BM 128
#define BN 128
#define BK 16

__global__ void __launch_bounds__(256)
gemm_kernel(const float* __restrict__ A, const float* __restrict__ B,
            float* __restrict__ C, int M, int N, int K,
            const float* __restrict__ bias)
{
    __shared__ float As[BK][BM];   // A transposed tile
    __shared__ float Bs[BK][BN];

    const int tid = threadIdx.x;
    const int bm = blockIdx.y, bn = blockIdx.x;
    const int tr = tid >> 4, tc = tid & 15;

    const float* Ab = A + (size_t)bm * BM * K;
    const float* Bb = B + (size_t)bn * BN;

    float acc[8][8];
#pragma unroll
    for (int i = 0; i < 8; i++)
#pragma unroll
        for (int j = 0; j < 8; j++) acc[i][j] = 0.f;

    for (int k0 = 0; k0 < K; k0 += BK) {
        // Load A tile (128x16): 512 float4, 2 per thread, store transposed
#pragma unroll
        for (int p = 0; p < 2; p++) {
            int t = tid + p * 256;
            int ar = t >> 2, ac4 = t & 3;
            float4 v = *reinterpret_cast<const float4*>(
                Ab + (size_t)ar * K + k0 + ac4 * 4);
            As[ac4 * 4 + 0][ar] = v.x;
            As[ac4 * 4 + 1][ar] = v.y;
            As[ac4 * 4 + 2][ar] = v.z;
            As[ac4 * 4 + 3][ar] = v.w;
        }
        // Load B tile (16x128): 512 float4, 2 per thread
#pragma unroll
        for (int p = 0; p < 2; p++) {
            int t = tid + p * 256;
            int br = t >> 5, bc4 = t & 31;
            *reinterpret_cast<float4*>(&Bs[br][bc4 * 4]) =
                *reinterpret_cast<const float4*>(
                    Bb + (size_t)(k0 + br) * N + bc4 * 4);
        }
        __syncthreads();

#pragma unroll
        for (int k = 0; k < BK; k++) {
            float a[8], b[8];
            *(float4*)&a[0] = *(float4*)&As[k][tr * 8];
            *(float4*)&a[4] = *(float4*)&As[k][tr * 8 + 4];
            *(float4*)&b[0] = *(float4*)&Bs[k][tc * 8];
            *(float4*)&b[4] = *(float4*)&Bs[k][tc * 8 + 4];
#pragma unroll
            for (int i = 0; i < 8; i++)
#pragma unroll
                for (int j = 0; j < 8; j++)
                    acc[i][j] += a[i] * b[j];
        }
        __syncthreads();
    }

    const int crow0 = bm * BM + tr * 8;
    const int ccol0 = bn * BN + tc * 8;
    float bv[8];
#pragma unroll
    for (int j = 0; j < 8; j++) bv[j] = bias ? bias[ccol0 + j] : 0.f;

#pragma unroll
    for (int i = 0; i < 8; i++) {
        float* Crow = C + (size_t)(crow0 + i) * N + ccol0;
        float4 o0 = make_float4(acc[i][0] + bv[0], acc[i][1] + bv[1],
                                acc[i][2] + bv[2], acc[i][3] + bv[3]);
        float4 o1 = make_float4(acc[i][4] + bv[4], acc[i][5] + bv[5],
                                acc[i][6] + bv[6], acc[i][7] + bv[7]);
        *reinterpret_cast<float4*>(Crow)     = o0;
        *reinterpret_cast<float4*>(Crow + 4) = o1;
    }
}

// ---------------------------------------------------------------------------
// Flash attention, causal. One CTA per (b, h, q-tile of 64 rows).
// 256 threads: 16x16 thread grid, 4x4 microtiles for both S (64x64) and O
// (64 rows x 64 dims). Online softmax in fp32. KV tiles 64x64 in shared.
// qkv layout: row (b*L + l), cols [h*64 .. +64) = Q, +1024 = K, +2048 = V.
// Output written directly as (B*L, D): out[(b*L+l)*1024 + h*64 + d].
// ---------------------------------------------------------------------------
#define SQ_STR 64
#define SKV_STR 65
// dynamic smem floats: sQ 64*64, sK 64*65, sV 64*65, sP 64*64
#define ATTN_SMEM_FLOATS (64 * SQ_STR + 2 * 64 * SKV_STR + 64 * SQ_STR)

__global__ void __launch_bounds__(256)
attn_kernel(const float* __restrict__ qkv, float* __restrict__ out)
{
    extern __shared__ float sm[];
    float* sQ = sm;                       // stride 64
    float* sK = sQ + 64 * SQ_STR;         // stride 65
    float* sV = sK + 64 * SKV_STR;        // stride 65
    float* sP = sV + 64 * SKV_STR;        // stride 64

    const int tid = threadIdx.x;
    const int qt = 31 - (int)blockIdx.x;  // heavy q-tiles first
    const int bh = blockIdx.y;
    const int b = bh >> 4, h = bh & 15;
    const float* base = qkv + (size_t)b * LSEQ * QKVN + h * HDIM;
    const int q0 = qt * 64;

    // Load Q tile: 64 rows x 64 floats = 1024 float4, 4 per thread
#pragma unroll
    for (int p = 0; p < 4; p++) {
        int t = tid + p * 256;
        int r = t >> 4, c4 = t & 15;
        *reinterpret_cast<float4*>(&sQ[r * SQ_STR + c4 * 4]) =
            *reinterpret_cast<const float4*>(
                base + (size_t)(q0 + r) * QKVN + c4 * 4);
    }

    const int tr = tid >> 4, tc = tid & 15;
    const int r0 = tr * 4, c0 = tc * 4;

    float acc[4][4];
#pragma unroll
    for (int i = 0; i < 4; i++)
#pragma unroll
        for (int j = 0; j < 4; j++) acc[i][j] = 0.f;
    float mrow[4], lrow[4];
#pragma unroll
    for (int i = 0; i < 4; i++) { mrow[i] = -1e30f; lrow[i] = 0.f; }

    const float scale = 0.125f;  // hd^-0.5, hd=64

    for (int kt = 0; kt <= qt; kt++) {
        const int k0 = kt * 64;
        __syncthreads();  // previous iter's sP/sV reads done; Q load visible

        // Load K,V tiles (64x64 each)
#pragma unroll
        for (int p = 0; p < 4; p++) {
            int t = tid + p * 256;
            int r = t >> 4, c4 = t & 15;
            const float* rowp = base + (size_t)(k0 + r) * QKVN + c4 * 4;
            float4 kv = *reinterpret_cast<const float4*>(rowp + DMODEL);
            float4 vv = *reinterpret_cast<const float4*>(rowp + 2 * DMODEL);
            float* kd = &sK[r * SKV_STR + c4 * 4];
            kd[0] = kv.x; kd[1] = kv.y; kd[2] = kv.z; kd[3] = kv.w;
            float* vd = &sV[r * SKV_STR + c4 * 4];
            vd[0] = vv.x; vd[1] = vv.y; vd[2] = vv.z; vd[3] = vv.w;
        }
        __syncthreads();

        // S = Q @ K^T, 4x4 per thread
        float s[4][4];
#pragma unroll
        for (int i = 0; i < 4; i++)
#pragma unroll
            for (int j = 0; j < 4; j++) s[i][j] = 0.f;

#pragma unroll 8
        for (int k = 0; k < 64; k++) {
            float a0 = sQ[(r0 + 0) * SQ_STR + k];
            float a1 = sQ[(r0 + 1) * SQ_STR + k];
            float a2 = sQ[(r0 + 2) * SQ_STR + k];
            float a3 = sQ[(r0 + 3) * SQ_STR + k];
            float b0 = sK[(c0 + 0) * SKV_STR + k];
            float b1 = sK[(c0 + 1) * SKV_STR + k];
            float b2 = sK[(c0 + 2) * SKV_STR + k];
            float b3 = sK[(c0 + 3) * SKV_STR + k];
            s[0][0] += a0 * b0; s[0][1] += a0 * b1; s[0][2] += a0 * b2; s[0][3] += a0 * b3;
            s[1][0] += a1 * b0; s[1][1] += a1 * b1; s[1][2] += a1 * b2; s[1][3] += a1 * b3;
            s[2][0] += a2 * b0; s[2][1] += a2 * b1; s[2][2] += a2 * b2; s[2][3] += a2 * b3;
            s[3][0] += a3 * b0; s[3][1] += a3 * b1; s[3][2] += a3 * b2; s[3][3] += a3 * b3;
        }

        const bool diag = (kt == qt);
#pragma unroll
        for (int i = 0; i < 4; i++)
#pragma unroll
            for (int j = 0; j < 4; j++) {
                float v = s[i][j] * scale;
                if (diag && (c0 + j > r0 + i)) v = -1e30f;
                s[i][j] = v;
            }

        // Online softmax update (per row; 16 lanes per row-group reduce)
#pragma unroll
        for (int i = 0; i < 4; i++) {
            float mt = fmaxf(fmaxf(s[i][0], s[i][1]), fmaxf(s[i][2], s[i][3]));
#pragma unroll
            for (int off = 8; off > 0; off >>= 1)
                mt = fmaxf(mt, __shfl_xor_sync(0xffffffffu, mt, off));
            float mnew = fmaxf(mrow[i], mt);
            float corr = __expf(mrow[i] - mnew);
            mrow[i] = mnew;
            float rs = 0.f;
#pragma unroll
            for (int j = 0; j < 4; j++) {
                float p = __expf(s[i][j] - mnew);
                s[i][j] = p;
                rs += p;
            }
#pragma unroll
            for (int off = 8; off > 0; off >>= 1)
                rs += __shfl_xor_sync(0xffffffffu, rs, off);
            lrow[i] = lrow[i] * corr + rs;
#pragma unroll
            for (int j = 0; j < 4; j++) acc[i][j] *= corr;
            // stage P
#pragma unroll
            for (int j = 0; j < 4; j++)
                sP[(r0 + i) * SQ_STR + c0 + j] = s[i][j];
        }
        __syncthreads();

        // O += P @ V
#pragma unroll 8
        for (int k = 0; k < 64; k++) {
            float p0 = sP[(r0 + 0) * SQ_STR + k];
            float p1 = sP[(r0 + 1) * SQ_STR + k];
            float p2 = sP[(r0 + 2) * SQ_STR + k];
            float p3 = sP[(r0 + 3) * SQ_STR + k];
            float v0 = sV[k * SKV_STR + c0 + 0];
            float v1 = sV[k * SKV_STR + c0 + 1];
            float v2 = sV[k * SKV_STR + c0 + 2];
            float v3 = sV[k * SKV_STR + c0 + 3];
            acc[0][0] += p0 * v0; acc[0][1] += p0 * v1; acc[0][2] += p0 * v2; acc[0][3] += p0 * v3;
            acc[1][0] += p1 * v0; acc[1][1] += p1 * v1; acc[1][2] += p1 * v2; acc[1][3] += p1 * v3;
            acc[2][0] += p2 * v0; acc[2][1] += p2 * v1; acc[2][2] += p2 * v2; acc[2][3] += p2 * v3;
            acc[3][0] += p3 * v0; acc[3][1] += p3 * v1; acc[3][2] += p3 * v2; acc[3][3] += p3 * v3;
        }
    }

    // Epilogue: normalize and write to (B*L, D) layout
#pragma unroll
    for (int i = 0; i < 4; i++) {
        float inv = 1.0f / lrow[i];
        int row = q0 + r0 + i;
        float* op = out + (size_t)(b * LSEQ + row) * DMODEL + h * HDIM + c0;
        float4 o = make_float4(acc[i][0] * inv, acc[i][1] * inv,
                               acc[i][2] * inv, acc[i][3] * inv);
        *reinterpret_cast<float4*>(op) = o;
    }
}

// ---------------------------------------------------------------------------
extern "C" void kernel_launch(void* const* d_in, const int* in_sizes, int n_in,
                              void* d_out, int out_size)
{
    (void)in_sizes; (void)n_in; (void)out_size;
    const float* x      = (const float*)d_in[0];
    // d_in[1] = attn_mask (always causal triu(k=1); implemented directly)
    const float* w_qkv  = (const float*)d_in[2];
    const float* w_proj = (const float*)d_in[3];
    const float* b_proj = (const float*)d_in[4];
    float* out = (float*)d_out;

    float* qkv_p = nullptr;
    float* attn_p = nullptr;
    cudaGetSymbolAddress((void**)&qkv_p, g_qkv);
    cudaGetSymbolAddress((void**)&attn_p, g_attn);

    const int smem_bytes = ATTN_SMEM_FLOATS * (int)sizeof(float);
    cudaFuncSetAttribute(attn_kernel,
                         cudaFuncAttributeMaxDynamicSharedMemorySize,
                         smem_bytes);

    // 1) QKV GEMM: (8192,1024) @ (1024,3072)
    {
        dim3 grid(QKVN / BN, MROWS / BM);
        gemm_kernel<<<grid, 256>>>(x, w_qkv, qkv_p, MROWS, QKVN, DMODEL,
                                   nullptr);
    }
    // 2) Causal flash attention
    {
        dim3 grid(LSEQ / 64, BB * NH);
        attn_kernel<<<grid, 256, smem_bytes>>>(qkv_p, attn_p);
    }
    // 3) Output projection + bias: (8192,1024) @ (1024,1024)
    {
        dim3 grid(DMODEL / BN, MROWS / BM);
        gemm_kernel<<<grid, 256>>>(attn_p, w_proj, out, MROWS, DMODEL, DMODEL,
                                   b_proj);
    }
}

// round 5
// speedup vs baseline: 1.0555x; 1.0555x over previous
#include <cuda_runtime.h>
#include <cuda_bf16.h>
#include <cstddef>
#include <math.h>

// Problem constants
#define BB 4
#define LSEQ 2048
#define DMODEL 1024
#define NH 16
#define HDIM 64
#define MROWS (BB * LSEQ)      // 8192
#define QKVN (3 * DMODEL)      // 3072

// Scratch (static device arrays; no allocation APIs allowed)
__device__ float g_qkv[(size_t)MROWS * QKVN];    // (B*L, 3D)
__device__ float g_attn[(size_t)MROWS * DMODEL]; // (B*L, D) attention output

// ---------------------------------------------------------------------------
// Tiled fp32 GEMM: C[M,N] = A[M,K] @ B[K,N] (+bias). BM=BN=128, BK=16,
// 256 threads, 8x8 per-thread microtile.
// ---------------------------------------------------------------------------
#define BM 128
#define BN 128
#define BK 16

__global__ void __launch_bounds__(256)
gemm_kernel(const float* __restrict__ A, const float* __restrict__ B,
            float* __restrict__ C, int M, int N, int K,
            const float* __restrict__ bias)
{
    __shared__ float As[BK][BM];   // A transposed tile
    __shared__ float Bs[BK][BN];

    const int tid = threadIdx.x;
    const int bm = blockIdx.y, bn = blockIdx.x;
    const int tr = tid >> 4, tc = tid & 15;

    const float* Ab = A + (size_t)bm * BM * K;
    const float* Bb = B + (size_t)bn * BN;

    float acc[8][8];
#pragma unroll
    for (int i = 0; i < 8; i++)
#pragma unroll
        for (int j = 0; j < 8; j++) acc[i][j] = 0.f;

    for (int k0 = 0; k0 < K; k0 += BK) {
        // Load A tile (128x16): 512 float4, 2 per thread, store transposed
#pragma unroll
        for (int p = 0; p < 2; p++) {
            int t = tid + p * 256;
            int ar = t >> 2, ac4 = t & 3;
            float4 v = *reinterpret_cast<const float4*>(
                Ab + (size_t)ar * K + k0 + ac4 * 4);
            As[ac4 * 4 + 0][ar] = v.x;
            As[ac4 * 4 + 1][ar] = v.y;
            As[ac4 * 4 + 2][ar] = v.z;
            As[ac4 * 4 + 3][ar] = v.w;
        }
        // Load B tile (16x128): 512 float4, 2 per thread
#pragma unroll
        for (int p = 0; p < 2; p++) {
            int t = tid + p * 256;
            int br = t >> 5, bc4 = t & 31;
            *reinterpret_cast<float4*>(&Bs[br][bc4 * 4]) =
                *reinterpret_cast<const float4*>(
                    Bb + (size_t)(k0 + br) * N + bc4 * 4);
        }
        __syncthreads();

#pragma unroll
        for (int k = 0; k < BK; k++) {
            float a[8], b[8];
            *(float4*)&a[0] = *(float4*)&As[k][tr * 8];
            *(float4*)&a[4] = *(float4*)&As[k][tr * 8 + 4];
            *(float4*)&b[0] = *(float4*)&Bs[k][tc * 8];
            *(float4*)&b[4] = *(float4*)&Bs[k][tc * 8 + 4];
#pragma unroll
            for (int i = 0; i < 8; i++)
#pragma unroll
                for (int j = 0; j < 8; j++)
                    acc[i][j] += a[i] * b[j];
        }
        __syncthreads();
    }

    const int crow0 = bm * BM + tr * 8;
    const int ccol0 = bn * BN + tc * 8;
    float bv[8];
#pragma unroll
    for (int j = 0; j < 8; j++) bv[j] = bias ? bias[ccol0 + j] : 0.f;

#pragma unroll
    for (int i = 0; i < 8; i++) {
        float* Crow = C + (size_t)(crow0 + i) * N + ccol0;
        float4 o0 = make_float4(acc[i][0] + bv[0], acc[i][1] + bv[1],
                                acc[i][2] + bv[2], acc[i][3] + bv[3]);
        float4 o1 = make_float4(acc[i][4] + bv[4], acc[i][5] + bv[5],
                                acc[i][6] + bv[6], acc[i][7] + bv[7]);
        *reinterpret_cast<float4*>(Crow)     = o0;
        *reinterpret_cast<float4*>(Crow + 4) = o1;
    }
}

// ---------------------------------------------------------------------------
// Flash attention, causal. One CTA per (b, h, q-tile of 64 rows).
// 256 threads: 16x16 thread grid, 4x4 microtiles for both S (64x64) and O
// (64 rows x 64 dims). Online softmax in fp32. KV tiles 64x64 in shared.
// qkv layout: row (b*L + l), cols [h*64 .. +64) = Q, +1024 = K, +2048 = V.
// Output written directly as (B*L, D): out[(b*L+l)*1024 + h*64 + d].
// ---------------------------------------------------------------------------
#define SQ_STR 64
#define SKV_STR 65
// dynamic smem floats: sQ 64*64, sK 64*65, sV 64*65, sP 64*64
#define ATTN_SMEM_FLOATS (64 * SQ_STR + 2 * 64 * SKV_STR + 64 * SQ_STR)

__global__ void __launch_bounds__(256)
attn_kernel(const float* __restrict__ qkv, float* __restrict__ out)
{
    extern __shared__ float sm[];
    float* sQ = sm;                       // stride 64
    float* sK = sQ + 64 * SQ_STR;         // stride 65
    float* sV = sK + 64 * SKV_STR;        // stride 65
    float* sP = sV + 64 * SKV_STR;        // stride 64

    const int tid = threadIdx.x;
    const int qt = 31 - (int)blockIdx.x;  // heavy q-tiles first
    const int bh = blockIdx.y;
    const int b = bh >> 4, h = bh & 15;
    const float* base = qkv + (size_t)b * LSEQ * QKVN + h * HDIM;
    const int q0 = qt * 64;

    // Load Q tile: 64 rows x 64 floats = 1024 float4, 4 per thread
#pragma unroll
    for (int p = 0; p < 4; p++) {
        int t = tid + p * 256;
        int r = t >> 4, c4 = t & 15;
        *reinterpret_cast<float4*>(&sQ[r * SQ_STR + c4 * 4]) =
            *reinterpret_cast<const float4*>(
                base + (size_t)(q0 + r) * QKVN + c4 * 4);
    }

    const int tr = tid >> 4, tc = tid & 15;
    const int r0 = tr * 4, c0 = tc * 4;

    float acc[4][4];
#pragma unroll
    for (int i = 0; i < 4; i++)
#pragma unroll
        for (int j = 0; j < 4; j++) acc[i][j] = 0.f;
    float mrow[4], lrow[4];
#pragma unroll
    for (int i = 0; i < 4; i++) { mrow[i] = -1e30f; lrow[i] = 0.f; }

    const float scale = 0.125f;  // hd^-0.5, hd=64

    for (int kt = 0; kt <= qt; kt++) {
        const int k0 = kt * 64;
        __syncthreads();  // previous iter's sP/sV reads done; Q load visible

        // Load K,V tiles (64x64 each)
#pragma unroll
        for (int p = 0; p < 4; p++) {
            int t = tid + p * 256;
            int r = t >> 4, c4 = t & 15;
            const float* rowp = base + (size_t)(k0 + r) * QKVN + c4 * 4;
            float4 kv = *reinterpret_cast<const float4*>(rowp + DMODEL);
            float4 vv = *reinterpret_cast<const float4*>(rowp + 2 * DMODEL);
            float* kd = &sK[r * SKV_STR + c4 * 4];
            kd[0] = kv.x; kd[1] = kv.y; kd[2] = kv.z; kd[3] = kv.w;
            float* vd = &sV[r * SKV_STR + c4 * 4];
            vd[0] = vv.x; vd[1] = vv.y; vd[2] = vv.z; vd[3] = vv.w;
        }
        __syncthreads();

        // S = Q @ K^T, 4x4 per thread
        float s[4][4];
#pragma unroll
        for (int i = 0; i < 4; i++)
#pragma unroll
            for (int j = 0; j < 4; j++) s[i][j] = 0.f;

#pragma unroll 8
        for (int k = 0; k < 64; k++) {
            float a0 = sQ[(r0 + 0) * SQ_STR + k];
            float a1 = sQ[(r0 + 1) * SQ_STR + k];
            float a2 = sQ[(r0 + 2) * SQ_STR + k];
            float a3 = sQ[(r0 + 3) * SQ_STR + k];
            float b0 = sK[(c0 + 0) * SKV_STR + k];
            float b1 = sK[(c0 + 1) * SKV_STR + k];
            float b2 = sK[(c0 + 2) * SKV_STR + k];
            float b3 = sK[(c0 + 3) * SKV_STR + k];
            s[0][0] += a0 * b0; s[0][1] += a0 * b1; s[0][2] += a0 * b2; s[0][3] += a0 * b3;
            s[1][0] += a1 * b0; s[1][1] += a1 * b1; s[1][2] += a1 * b2; s[1][3] += a1 * b3;
            s[2][0] += a2 * b0; s[2][1] += a2 * b1; s[2][2] += a2 * b2; s[2][3] += a2 * b3;
            s[3][0] += a3 * b0; s[3][1] += a3 * b1; s[3][2] += a3 * b2; s[3][3] += a3 * b3;
        }

        const bool diag = (kt == qt);
#pragma unroll
        for (int i = 0; i < 4; i++)
#pragma unroll
            for (int j = 0; j < 4; j++) {
                float v = s[i][j] * scale;
                if (diag && (c0 + j > r0 + i)) v = -1e30f;
                s[i][j] = v;
            }

        // Online softmax update (per row; 16 lanes per row-group reduce)
#pragma unroll
        for (int i = 0; i < 4; i++) {
            float mt = fmaxf(fmaxf(s[i][0], s[i][1]), fmaxf(s[i][2], s[i][3]));
#pragma unroll
            for (int off = 8; off > 0; off >>= 1)
                mt = fmaxf(mt, __shfl_xor_sync(0xffffffffu, mt, off));
            float mnew = fmaxf(mrow[i], mt);
            float corr = __expf(mrow[i] - mnew);
            mrow[i] = mnew;
            float rs = 0.f;
#pragma unroll
            for (int j = 0; j < 4; j++) {
                float p = __expf(s[i][j] - mnew);
                s[i][j] = p;
                rs += p;
            }
#pragma unroll
            for (int off = 8; off > 0; off >>= 1)
                rs += __shfl_xor_sync(0xffffffffu, rs, off);
            lrow[i] = lrow[i] * corr + rs;
#pragma unroll
            for (int j = 0; j < 4; j++) acc[i][j] *= corr;
            // stage P
#pragma unroll
            for (int j = 0; j < 4; j++)
                sP[(r0 + i) * SQ_STR + c0 + j] = s[i][j];
        }
        __syncthreads();

        // O += P @ V
#pragma unroll 8
        for (int k = 0; k < 64; k++) {
            float p0 = sP[(r0 + 0) * SQ_STR + k];
            float p1 = sP[(r0 + 1) * SQ_STR + k];
            float p2 = sP[(r0 + 2) * SQ_STR + k];
            float p3 = sP[(r0 + 3) * SQ_STR + k];
            float v0 = sV[k * SKV_STR + c0 + 0];
            float v1 = sV[k * SKV_STR + c0 + 1];
            float v2 = sV[k * SKV_STR + c0 + 2];
            float v3 = sV[k * SKV_STR + c0 + 3];
            acc[0][0] += p0 * v0; acc[0][1] += p0 * v1; acc[0][2] += p0 * v2; acc[0][3] += p0 * v3;
            acc[1][0] += p1 * v0; acc[1][1] += p1 * v1; acc[1][2] += p1 * v2; acc[1][3] += p1 * v3;
            acc[2][0] += p2 * v0; acc[2][1] += p2 * v1; acc[2][2] += p2 * v2; acc[2][3] += p2 * v3;
            acc[3][0] += p3 * v0; acc[3][1] += p3 * v1; acc[3][2] += p3 * v2; acc[3][3] += p3 * v3;
        }
    }

    // Epilogue: normalize and write to (B*L, D) layout
#pragma unroll
    for (int i = 0; i < 4; i++) {
        float inv = 1.0f / lrow[i];
        int row = q0 + r0 + i;
        float* op = out + (size_t)(b * LSEQ + row) * DMODEL + h * HDIM + c0;
        float4 o = make_float4(acc[i][0] * inv, acc[i][1] * inv,
                               acc[i][2] * inv, acc[i][3] * inv);
        *reinterpret_cast<float4*>(op) = o;
    }
}

// ---------------------------------------------------------------------------
extern "C" void kernel_launch(void* const* d_in, const int* in_sizes, int n_in,
                              void* d_out, int out_size)
{
    (void)in_sizes; (void)n_in; (void)out_size;
    const float* x      = (const float*)d_in[0];
    // d_in[1] = attn_mask (always causal triu(k=1); implemented directly)
    const float* w_qkv  = (const float*)d_in[2];
    const float* w_proj = (const float*)d_in[3];
    const float* b_proj = (const float*)d_in[4];
    float* out = (float*)d_out;

    float* qkv_p = nullptr;
    float* attn_p = nullptr;
    cudaGetSymbolAddress((void**)&qkv_p, g_qkv);
    cudaGetSymbolAddress((void**)&attn_p, g_attn);

    const int smem_bytes = ATTN_SMEM_FLOATS * (int)sizeof(float);
    cudaFuncSetAttribute(attn_kernel,
                         cudaFuncAttributeMaxDynamicSharedMemorySize,
                         smem_bytes);

    // 1) QKV GEMM: (8192,1024) @ (1024,3072)
    {
        dim3 grid(QKVN / BN, MROWS / BM);
        gemm_kernel<<<grid, 256>>>(x, w_qkv, qkv_p, MROWS, QKVN, DMODEL,
                                   nullptr);
    }
    // 2) Causal flash attention
    {
        dim3 grid(LSEQ / 64, BB * NH);
        attn_kernel<<<grid, 256, smem_bytes>>>(qkv_p, attn_p);
    }
    // 3) Output projection + bias: (8192,1024) @ (1024,1024)
    {
        dim3 grid(DMODEL / BN, MROWS / BM);
        gemm_kernel<<<grid, 256>>>(attn_p, w_proj, out, MROWS, DMODEL, DMODEL,
                                   b_proj);
    }
}

// round 6
// speedup vs baseline: 1.2946x; 1.2266x over previous
#include <cuda_runtime.h>
#include <cuda_bf16.h>
#include <cstddef>
#include <cstdint>
#include <math.h>

// Problem constants
#define BB 4
#define LSEQ 2048
#define DMODEL 1024
#define NH 16
#define HDIM 64
#define MROWS (BB * LSEQ)      // 8192
#define QKVN (3 * DMODEL)      // 3072

// Scratch (static device arrays; no allocation APIs allowed)
__device__ float g_qkv[(size_t)MROWS * QKVN];    // (B*L, 3D)
__device__ float g_attn[(size_t)MROWS * DMODEL]; // (B*L, D) attention output

// ---------------------------------------------------------------------------
// TF32 tensor-core GEMM: C[M,N] = A[M,K] @ B[K,N] (+bias).
// CTA tile 128x128x32, 8 warps (4 M x 2 N), warp tile 32x64.
// mma.sync.aligned.m16n8k8.row.col.f32.tf32.tf32.f32
// Smem layouts conflict-free for fragment gathers:
//   As[128][36]  : frag addr bank = (4*g + t) mod 32  -> 32 distinct
//   Bs[32][136]  : frag addr bank = (8*t + g) mod 32  -> 32 distinct
// ---------------------------------------------------------------------------
#define GBM 128
#define GBN 128
#define GBK 32
#define ASTR 36
#define BSTR 136

__device__ __forceinline__ float tf32r(float x) {
    float y;
    asm("cvt.rna.tf32.f32 %0, %1;" : "=f"(y) : "f"(x));
    return y;
}

__device__ __forceinline__ void mma_tf32(float* d, const uint32_t* a,
                                         const uint32_t* b) {
    asm volatile(
        "mma.sync.aligned.m16n8k8.row.col.f32.tf32.tf32.f32 "
        "{%0,%1,%2,%3}, {%4,%5,%6,%7}, {%8,%9}, {%0,%1,%2,%3};\n"
        : "+f"(d[0]), "+f"(d[1]), "+f"(d[2]), "+f"(d[3])
        : "r"(a[0]), "r"(a[1]), "r"(a[2]), "r"(a[3]), "r"(b[0]), "r"(b[1]));
}

__global__ void __launch_bounds__(256, 2)
gemm_tf32_kernel(const float* __restrict__ A, const float* __restrict__ B,
                 float* __restrict__ C, int M, int N, int K,
                 const float* __restrict__ bias)
{
    __shared__ float As[GBM][ASTR];
    __shared__ float Bs[GBK][BSTR];

    const int tid = threadIdx.x;
    const int lane = tid & 31;
    const int warp = tid >> 5;
    const int wm = (warp & 3) * 32;   // warp M offset within CTA tile
    const int wn = (warp >> 2) * 64;  // warp N offset
    const int g = lane >> 2;          // group id (0..7)
    const int t = lane & 3;           // thread-in-group (0..3)

    const float* Ab = A + (size_t)blockIdx.y * GBM * K;
    const float* Bb = B + (size_t)blockIdx.x * GBN;

    float acc[2][8][4];
#pragma unroll
    for (int mi = 0; mi < 2; mi++)
#pragma unroll
        for (int ni = 0; ni < 8; ni++)
#pragma unroll
            for (int q = 0; q < 4; q++) acc[mi][ni][q] = 0.f;

    for (int k0 = 0; k0 < K; k0 += GBK) {
        // Load A tile (128x32) -> As, tf32-rounded. 1024 float4, 4/thread.
#pragma unroll
        for (int p = 0; p < 4; p++) {
            int tt = tid + p * 256;
            int r = tt >> 3, c4 = (tt & 7) * 4;
            float4 v = *reinterpret_cast<const float4*>(
                Ab + (size_t)r * K + k0 + c4);
            As[r][c4 + 0] = tf32r(v.x);
            As[r][c4 + 1] = tf32r(v.y);
            As[r][c4 + 2] = tf32r(v.z);
            As[r][c4 + 3] = tf32r(v.w);
        }
        // Load B tile (32x128) -> Bs, tf32-rounded. 1024 float4, 4/thread.
#pragma unroll
        for (int p = 0; p < 4; p++) {
            int tt = tid + p * 256;
            int r = tt >> 5, c4 = (tt & 31) * 4;
            float4 v = *reinterpret_cast<const float4*>(
                Bb + (size_t)(k0 + r) * N + c4);
            Bs[r][c4 + 0] = tf32r(v.x);
            Bs[r][c4 + 1] = tf32r(v.y);
            Bs[r][c4 + 2] = tf32r(v.z);
            Bs[r][c4 + 3] = tf32r(v.w);
        }
        __syncthreads();

#pragma unroll
        for (int ks = 0; ks < GBK / 8; ks++) {
            const int kk = ks * 8;
            uint32_t af[2][4];
#pragma unroll
            for (int mi = 0; mi < 2; mi++) {
                int r = wm + mi * 16 + g;
                af[mi][0] = __float_as_uint(As[r][kk + t]);
                af[mi][1] = __float_as_uint(As[r + 8][kk + t]);
                af[mi][2] = __float_as_uint(As[r][kk + t + 4]);
                af[mi][3] = __float_as_uint(As[r + 8][kk + t + 4]);
            }
            uint32_t bf[8][2];
#pragma unroll
            for (int ni = 0; ni < 8; ni++) {
                int c = wn + ni * 8 + g;
                bf[ni][0] = __float_as_uint(Bs[kk + t][c]);
                bf[ni][1] = __float_as_uint(Bs[kk + t + 4][c]);
            }
#pragma unroll
            for (int mi = 0; mi < 2; mi++)
#pragma unroll
                for (int ni = 0; ni < 8; ni++)
                    mma_tf32(acc[mi][ni], af[mi], bf[ni]);
        }
        __syncthreads();
    }

    // Epilogue: C fragment layout c0..c3 = (g, 2t), (g, 2t+1), (g+8, 2t), (g+8, 2t+1)
    const int row0 = blockIdx.y * GBM + wm;
    const int col0 = blockIdx.x * GBN + wn;
#pragma unroll
    for (int mi = 0; mi < 2; mi++) {
        int r = row0 + mi * 16 + g;
#pragma unroll
        for (int ni = 0; ni < 8; ni++) {
            int c = col0 + ni * 8 + t * 2;
            float b0 = 0.f, b1 = 0.f;
            if (bias) { b0 = bias[c]; b1 = bias[c + 1]; }
            float2 o0 = make_float2(acc[mi][ni][0] + b0, acc[mi][ni][1] + b1);
            float2 o1 = make_float2(acc[mi][ni][2] + b0, acc[mi][ni][3] + b1);
            *reinterpret_cast<float2*>(C + (size_t)r * N + c) = o0;
            *reinterpret_cast<float2*>(C + (size_t)(r + 8) * N + c) = o1;
        }
    }
}

// ---------------------------------------------------------------------------
// Flash attention, causal. One CTA per (b, h, q-tile of 64 rows).
// 256 threads: 16x16 thread grid, 4x4 microtiles. Online softmax in fp32.
// ---------------------------------------------------------------------------
#define SQ_STR 64
#define SKV_STR 65
#define ATTN_SMEM_FLOATS (64 * SQ_STR + 2 * 64 * SKV_STR + 64 * SQ_STR)

__global__ void __launch_bounds__(256)
attn_kernel(const float* __restrict__ qkv, float* __restrict__ out)
{
    extern __shared__ float sm[];
    float* sQ = sm;                       // stride 64
    float* sK = sQ + 64 * SQ_STR;         // stride 65
    float* sV = sK + 64 * SKV_STR;        // stride 65
    float* sP = sV + 64 * SKV_STR;        // stride 64

    const int tid = threadIdx.x;
    const int qt = 31 - (int)blockIdx.x;  // heavy q-tiles first
    const int bh = blockIdx.y;
    const int b = bh >> 4, h = bh & 15;
    const float* base = qkv + (size_t)b * LSEQ * QKVN + h * HDIM;
    const int q0 = qt * 64;

#pragma unroll
    for (int p = 0; p < 4; p++) {
        int t = tid + p * 256;
        int r = t >> 4, c4 = t & 15;
        *reinterpret_cast<float4*>(&sQ[r * SQ_STR + c4 * 4]) =
            *reinterpret_cast<const float4*>(
                base + (size_t)(q0 + r) * QKVN + c4 * 4);
    }

    const int tr = tid >> 4, tc = tid & 15;
    const int r0 = tr * 4, c0 = tc * 4;

    float acc[4][4];
#pragma unroll
    for (int i = 0; i < 4; i++)
#pragma unroll
        for (int j = 0; j < 4; j++) acc[i][j] = 0.f;
    float mrow[4], lrow[4];
#pragma unroll
    for (int i = 0; i < 4; i++) { mrow[i] = -1e30f; lrow[i] = 0.f; }

    const float scale = 0.125f;

    for (int kt = 0; kt <= qt; kt++) {
        const int k0 = kt * 64;
        __syncthreads();

#pragma unroll
        for (int p = 0; p < 4; p++) {
            int t = tid + p * 256;
            int r = t >> 4, c4 = t & 15;
            const float* rowp = base + (size_t)(k0 + r) * QKVN + c4 * 4;
            float4 kv = *reinterpret_cast<const float4*>(rowp + DMODEL);
            float4 vv = *reinterpret_cast<const float4*>(rowp + 2 * DMODEL);
            float* kd = &sK[r * SKV_STR + c4 * 4];
            kd[0] = kv.x; kd[1] = kv.y; kd[2] = kv.z; kd[3] = kv.w;
            float* vd = &sV[r * SKV_STR + c4 * 4];
            vd[0] = vv.x; vd[1] = vv.y; vd[2] = vv.z; vd[3] = vv.w;
        }
        __syncthreads();

        float s[4][4];
#pragma unroll
        for (int i = 0; i < 4; i++)
#pragma unroll
            for (int j = 0; j < 4; j++) s[i][j] = 0.f;

#pragma unroll 8
        for (int k = 0; k < 64; k++) {
            float a0 = sQ[(r0 + 0) * SQ_STR + k];
            float a1 = sQ[(r0 + 1) * SQ_STR + k];
            float a2 = sQ[(r0 + 2) * SQ_STR + k];
            float a3 = sQ[(r0 + 3) * SQ_STR + k];
            float b0 = sK[(c0 + 0) * SKV_STR + k];
            float b1 = sK[(c0 + 1) * SKV_STR + k];
            float b2 = sK[(c0 + 2) * SKV_STR + k];
            float b3 = sK[(c0 + 3) * SKV_STR + k];
            s[0][0] += a0 * b0; s[0][1] += a0 * b1; s[0][2] += a0 * b2; s[0][3] += a0 * b3;
            s[1][0] += a1 * b0; s[1][1] += a1 * b1; s[1][2] += a1 * b2; s[1][3] += a1 * b3;
            s[2][0] += a2 * b0; s[2][1] += a2 * b1; s[2][2] += a2 * b2; s[2][3] += a2 * b3;
            s[3][0] += a3 * b0; s[3][1] += a3 * b1; s[3][2] += a3 * b2; s[3][3] += a3 * b3;
        }

        const bool diag = (kt == qt);
#pragma unroll
        for (int i = 0; i < 4; i++)
#pragma unroll
            for (int j = 0; j < 4; j++) {
                float v = s[i][j] * scale;
                if (diag && (c0 + j > r0 + i)) v = -1e30f;
                s[i][j] = v;
            }

#pragma unroll
        for (int i = 0; i < 4; i++) {
            float mt = fmaxf(fmaxf(s[i][0], s[i][1]), fmaxf(s[i][2], s[i][3]));
#pragma unroll
            for (int off = 8; off > 0; off >>= 1)
                mt = fmaxf(mt, __shfl_xor_sync(0xffffffffu, mt, off));
            float mnew = fmaxf(mrow[i], mt);
            float corr = __expf(mrow[i] - mnew);
            mrow[i] = mnew;
            float rs = 0.f;
#pragma unroll
            for (int j = 0; j < 4; j++) {
                float p = __expf(s[i][j] - mnew);
                s[i][j] = p;
                rs += p;
            }
#pragma unroll
            for (int off = 8; off > 0; off >>= 1)
                rs += __shfl_xor_sync(0xffffffffu, rs, off);
            lrow[i] = lrow[i] * corr + rs;
#pragma unroll
            for (int j = 0; j < 4; j++) acc[i][j] *= corr;
#pragma unroll
            for (int j = 0; j < 4; j++)
                sP[(r0 + i) * SQ_STR + c0 + j] = s[i][j];
        }
        __syncthreads();

#pragma unroll 8
        for (int k = 0; k < 64; k++) {
            float p0 = sP[(r0 + 0) * SQ_STR + k];
            float p1 = sP[(r0 + 1) * SQ_STR + k];
            float p2 = sP[(r0 + 2) * SQ_STR + k];
            float p3 = sP[(r0 + 3) * SQ_STR + k];
            float v0 = sV[k * SKV_STR + c0 + 0];
            float v1 = sV[k * SKV_STR + c0 + 1];
            float v2 = sV[k * SKV_STR + c0 + 2];
            float v3 = sV[k * SKV_STR + c0 + 3];
            acc[0][0] += p0 * v0; acc[0][1] += p0 * v1; acc[0][2] += p0 * v2; acc[0][3] += p0 * v3;
            acc[1][0] += p1 * v0; acc[1][1] += p1 * v1; acc[1][2] += p1 * v2; acc[1][3] += p1 * v3;
            acc[2][0] += p2 * v0; acc[2][1] += p2 * v1; acc[2][2] += p2 * v2; acc[2][3] += p2 * v3;
            acc[3][0] += p3 * v0; acc[3][1] += p3 * v1; acc[3][2] += p3 * v2; acc[3][3] += p3 * v3;
        }
    }

#pragma unroll
    for (int i = 0; i < 4; i++) {
        float inv = 1.0f / lrow[i];
        int row = q0 + r0 + i;
        float* op = out + (size_t)(b * LSEQ + row) * DMODEL + h * HDIM + c0;
        float4 o = make_float4(acc[i][0] * inv, acc[i][1] * inv,
                               acc[i][2] * inv, acc[i][3] * inv);
        *reinterpret_cast<float4*>(op) = o;
    }
}

// ---------------------------------------------------------------------------
extern "C" void kernel_launch(void* const* d_in, const int* in_sizes, int n_in,
                              void* d_out, int out_size)
{
    (void)in_sizes; (void)n_in; (void)out_size;
    const float* x      = (const float*)d_in[0];
    // d_in[1] = attn_mask (always causal triu(k=1); implemented directly)
    const float* w_qkv  = (const float*)d_in[2];
    const float* w_proj = (const float*)d_in[3];
    const float* b_proj = (const float*)d_in[4];
    float* out = (float*)d_out;

    float* qkv_p = nullptr;
    float* attn_p = nullptr;
    cudaGetSymbolAddress((void**)&qkv_p, g_qkv);
    cudaGetSymbolAddress((void**)&attn_p, g_attn);

    const int smem_bytes = ATTN_SMEM_FLOATS * (int)sizeof(float);
    cudaFuncSetAttribute(attn_kernel,
                         cudaFuncAttributeMaxDynamicSharedMemorySize,
                         smem_bytes);

    // 1) QKV GEMM: (8192,1024) @ (1024,3072)  [tf32 tensor cores]
    {
        dim3 grid(QKVN / GBN, MROWS / GBM);
        gemm_tf32_kernel<<<grid, 256>>>(x, w_qkv, qkv_p, MROWS, QKVN, DMODEL,
                                        nullptr);
    }
    // 2) Causal flash attention
    {
        dim3 grid(LSEQ / 64, BB * NH);
        attn_kernel<<<grid, 256, smem_bytes>>>(qkv_p, attn_p);
    }
    // 3) Output projection + bias: (8192,1024) @ (1024,1024) [tf32]
    {
        dim3 grid(DMODEL / GBN, MROWS / GBM);
        gemm_tf32_kernel<<<grid, 256>>>(attn_p, w_proj, out, MROWS, DMODEL,
                                        DMODEL, b_proj);
    }
}

// round 7
// speedup vs baseline: 3.4505x; 2.6654x over previous
#include <cuda_runtime.h>
#include <cuda_bf16.h>
#include <cstddef>
#include <cstdint>
#include <math.h>

// Problem constants
#define BB 4
#define LSEQ 2048
#define DMODEL 1024
#define NH 16
#define HDIM 64
#define MROWS (BB * LSEQ)      // 8192
#define QKVN (3 * DMODEL)      // 3072

// Scratch (static device arrays; no allocation APIs allowed)
__device__ float g_qkv[(size_t)MROWS * QKVN];    // (B*L, 3D)
__device__ float g_attn[(size_t)MROWS * DMODEL]; // (B*L, D) attention output

__device__ __forceinline__ float tf32r(float x) {
    float y;
    asm("cvt.rna.tf32.f32 %0, %1;" : "=f"(y) : "f"(x));
    return y;
}

__device__ __forceinline__ void mma_tf32(float* d, const uint32_t* a,
                                         const uint32_t* b) {
    asm volatile(
        "mma.sync.aligned.m16n8k8.row.col.f32.tf32.tf32.f32 "
        "{%0,%1,%2,%3}, {%4,%5,%6,%7}, {%8,%9}, {%0,%1,%2,%3};\n"
        : "+f"(d[0]), "+f"(d[1]), "+f"(d[2]), "+f"(d[3])
        : "r"(a[0]), "r"(a[1]), "r"(a[2]), "r"(a[3]), "r"(b[0]), "r"(b[1]));
}

// ---------------------------------------------------------------------------
// TF32 tensor-core GEMM: C[M,N] = A[M,K] @ B[K,N] (+bias).
// CTA tile 128x128x32, 8 warps (4 M x 2 N), warp tile 32x64.
// ---------------------------------------------------------------------------
#define GBM 128
#define GBN 128
#define GBK 32
#define ASTR 36
#define BSTR 136

__global__ void __launch_bounds__(256, 2)
gemm_tf32_kernel(const float* __restrict__ A, const float* __restrict__ B,
                 float* __restrict__ C, int M, int N, int K,
                 const float* __restrict__ bias)
{
    __shared__ float As[GBM][ASTR];
    __shared__ float Bs[GBK][BSTR];

    const int tid = threadIdx.x;
    const int lane = tid & 31;
    const int warp = tid >> 5;
    const int wm = (warp & 3) * 32;
    const int wn = (warp >> 2) * 64;
    const int g = lane >> 2;
    const int t = lane & 3;

    const float* Ab = A + (size_t)blockIdx.y * GBM * K;
    const float* Bb = B + (size_t)blockIdx.x * GBN;

    float acc[2][8][4];
#pragma unroll
    for (int mi = 0; mi < 2; mi++)
#pragma unroll
        for (int ni = 0; ni < 8; ni++)
#pragma unroll
            for (int q = 0; q < 4; q++) acc[mi][ni][q] = 0.f;

    for (int k0 = 0; k0 < K; k0 += GBK) {
#pragma unroll
        for (int p = 0; p < 4; p++) {
            int tt = tid + p * 256;
            int r = tt >> 3, c4 = (tt & 7) * 4;
            float4 v = *reinterpret_cast<const float4*>(
                Ab + (size_t)r * K + k0 + c4);
            As[r][c4 + 0] = tf32r(v.x);
            As[r][c4 + 1] = tf32r(v.y);
            As[r][c4 + 2] = tf32r(v.z);
            As[r][c4 + 3] = tf32r(v.w);
        }
#pragma unroll
        for (int p = 0; p < 4; p++) {
            int tt = tid + p * 256;
            int r = tt >> 5, c4 = (tt & 31) * 4;
            float4 v = *reinterpret_cast<const float4*>(
                Bb + (size_t)(k0 + r) * N + c4);
            Bs[r][c4 + 0] = tf32r(v.x);
            Bs[r][c4 + 1] = tf32r(v.y);
            Bs[r][c4 + 2] = tf32r(v.z);
            Bs[r][c4 + 3] = tf32r(v.w);
        }
        __syncthreads();

#pragma unroll
        for (int ks = 0; ks < GBK / 8; ks++) {
            const int kk = ks * 8;
            uint32_t af[2][4];
#pragma unroll
            for (int mi = 0; mi < 2; mi++) {
                int r = wm + mi * 16 + g;
                af[mi][0] = __float_as_uint(As[r][kk + t]);
                af[mi][1] = __float_as_uint(As[r + 8][kk + t]);
                af[mi][2] = __float_as_uint(As[r][kk + t + 4]);
                af[mi][3] = __float_as_uint(As[r + 8][kk + t + 4]);
            }
            uint32_t bf[8][2];
#pragma unroll
            for (int ni = 0; ni < 8; ni++) {
                int c = wn + ni * 8 + g;
                bf[ni][0] = __float_as_uint(Bs[kk + t][c]);
                bf[ni][1] = __float_as_uint(Bs[kk + t + 4][c]);
            }
#pragma unroll
            for (int mi = 0; mi < 2; mi++)
#pragma unroll
                for (int ni = 0; ni < 8; ni++)
                    mma_tf32(acc[mi][ni], af[mi], bf[ni]);
        }
        __syncthreads();
    }

    const int row0 = blockIdx.y * GBM + wm;
    const int col0 = blockIdx.x * GBN + wn;
#pragma unroll
    for (int mi = 0; mi < 2; mi++) {
        int r = row0 + mi * 16 + g;
#pragma unroll
        for (int ni = 0; ni < 8; ni++) {
            int c = col0 + ni * 8 + t * 2;
            float b0 = 0.f, b1 = 0.f;
            if (bias) { b0 = bias[c]; b1 = bias[c + 1]; }
            float2 o0 = make_float2(acc[mi][ni][0] + b0, acc[mi][ni][1] + b1);
            float2 o1 = make_float2(acc[mi][ni][2] + b0, acc[mi][ni][3] + b1);
            *reinterpret_cast<float2*>(C + (size_t)r * N + c) = o0;
            *reinterpret_cast<float2*>(C + (size_t)(r + 8) * N + c) = o1;
        }
    }
}

// ---------------------------------------------------------------------------
// Flash attention with tf32 tensor cores. Q-tile 128, KV-tile 64, 8 warps.
// Each warp owns 16 Q rows for S, softmax, P and O (P staging is warp-private
// in smem -> no CTA barrier around it, only __syncwarp).
// Smem layouts (floats):
//   sQP[128][68] : Q (tf32, pre-scaled by 0.125), aliased as P after Q-frag
//                  extraction. A-frag gather bank = 4g+t (conflict-free).
//   sK [64][68]  : B-frag gather bank = 4g+t (conflict-free).
//   sV [64][72]  : B-frag gather bank = 8t+g (conflict-free).
// ---------------------------------------------------------------------------
#define AQ_STR 68
#define AK_STR 68
#define AV_STR 72
#define BLKQ 128
#define ATTN_SMEM_FLOATS (BLKQ * AQ_STR + 64 * AK_STR + 64 * AV_STR)

__global__ void __launch_bounds__(256)
attn_mma_kernel(const float* __restrict__ qkv, float* __restrict__ out)
{
    extern __shared__ float sm[];
    float* sQP = sm;                         // 128 x 68 (Q, later P)
    float* sK  = sQP + BLKQ * AQ_STR;        // 64 x 68
    float* sV  = sK + 64 * AK_STR;           // 64 x 72

    const int tid = threadIdx.x;
    const int lane = tid & 31;
    const int warp = tid >> 5;
    const int g = lane >> 2;     // 0..7
    const int t = lane & 3;      // 0..3
    const int m0 = warp * 16;    // warp's Q-row block within tile

    const int qt = (int)(gridDim.x - 1) - (int)blockIdx.x;  // heavy first
    const int bh = blockIdx.y;
    const int b = bh >> 4, h = bh & 15;
    const float* base = qkv + (size_t)b * LSEQ * QKVN + h * HDIM;
    const int q0 = qt * BLKQ;

    // Load Q tile (128x64), fold scale (power of 2; tf32-exact), round tf32.
#pragma unroll
    for (int p = 0; p < 8; p++) {
        int tt = tid + p * 256;
        int r = tt >> 4, c4 = (tt & 15) * 4;
        float4 v = *reinterpret_cast<const float4*>(
            base + (size_t)(q0 + r) * QKVN + c4);
        float* dq = &sQP[r * AQ_STR + c4];
        dq[0] = tf32r(v.x * 0.125f);
        dq[1] = tf32r(v.y * 0.125f);
        dq[2] = tf32r(v.z * 0.125f);
        dq[3] = tf32r(v.w * 0.125f);
    }
    __syncthreads();

    // Hoist Q A-fragments into registers (warp reads only its own 16 rows).
    uint32_t aq[8][4];
#pragma unroll
    for (int ks = 0; ks < 8; ks++) {
        int kk = ks * 8;
        aq[ks][0] = __float_as_uint(sQP[(m0 + g) * AQ_STR + kk + t]);
        aq[ks][1] = __float_as_uint(sQP[(m0 + 8 + g) * AQ_STR + kk + t]);
        aq[ks][2] = __float_as_uint(sQP[(m0 + g) * AQ_STR + kk + t + 4]);
        aq[ks][3] = __float_as_uint(sQP[(m0 + 8 + g) * AQ_STR + kk + t + 4]);
    }

    float o[8][4];
#pragma unroll
    for (int nt = 0; nt < 8; nt++)
#pragma unroll
        for (int q = 0; q < 4; q++) o[nt][q] = 0.f;
    float mr0 = -1e30f, mr1 = -1e30f, l0 = 0.f, l1 = 0.f;

    const int row0g = q0 + m0 + g;
    const int row1g = row0g + 8;
    const int nkv = 2 * qt + 2;

    for (int kt = 0; kt < nkv; kt++) {
        const int k0 = kt * 64;
        __syncthreads();  // previous iter's sK/sV reads complete

        // Load K,V tiles (64x64 each), tf32-rounded.
#pragma unroll
        for (int p = 0; p < 4; p++) {
            int tt = tid + p * 256;
            int r = tt >> 4, c4 = (tt & 15) * 4;
            const float* rp = base + (size_t)(k0 + r) * QKVN + c4;
            float4 kv = *reinterpret_cast<const float4*>(rp + DMODEL);
            float4 vv = *reinterpret_cast<const float4*>(rp + 2 * DMODEL);
            float* kd = &sK[r * AK_STR + c4];
            kd[0] = tf32r(kv.x); kd[1] = tf32r(kv.y);
            kd[2] = tf32r(kv.z); kd[3] = tf32r(kv.w);
            float* vd = &sV[r * AV_STR + c4];
            vd[0] = tf32r(vv.x); vd[1] = tf32r(vv.y);
            vd[2] = tf32r(vv.z); vd[3] = tf32r(vv.w);
        }
        __syncthreads();

        // S = (Q*scale) @ K^T : warp computes 16x64
        float s[8][4];
#pragma unroll
        for (int nt = 0; nt < 8; nt++)
#pragma unroll
            for (int q = 0; q < 4; q++) s[nt][q] = 0.f;

#pragma unroll
        for (int ks = 0; ks < 8; ks++) {
            const int kk = ks * 8;
#pragma unroll
            for (int nt = 0; nt < 8; nt++) {
                uint32_t bf[2];
                bf[0] = __float_as_uint(sK[(nt * 8 + g) * AK_STR + kk + t]);
                bf[1] = __float_as_uint(sK[(nt * 8 + g) * AK_STR + kk + t + 4]);
                mma_tf32(s[nt], aq[ks], bf);
            }
        }

        // Causal mask (only tiles touching the diagonal)
        if (kt >= 2 * qt) {
#pragma unroll
            for (int nt = 0; nt < 8; nt++) {
                int cb = k0 + nt * 8 + 2 * t;
#pragma unroll
                for (int q = 0; q < 2; q++) {
                    if (cb + q > row0g) s[nt][q] = -1e30f;
                    if (cb + q > row1g) s[nt][2 + q] = -1e30f;
                }
            }
        }

        // Online softmax (rows g and g+8; quad-reduce over t lanes)
        float mt0 = -1e30f, mt1 = -1e30f;
#pragma unroll
        for (int nt = 0; nt < 8; nt++) {
            mt0 = fmaxf(mt0, fmaxf(s[nt][0], s[nt][1]));
            mt1 = fmaxf(mt1, fmaxf(s[nt][2], s[nt][3]));
        }
        mt0 = fmaxf(mt0, __shfl_xor_sync(0xffffffffu, mt0, 1));
        mt0 = fmaxf(mt0, __shfl_xor_sync(0xffffffffu, mt0, 2));
        mt1 = fmaxf(mt1, __shfl_xor_sync(0xffffffffu, mt1, 1));
        mt1 = fmaxf(mt1, __shfl_xor_sync(0xffffffffu, mt1, 2));

        float mn0 = fmaxf(mr0, mt0), mn1 = fmaxf(mr1, mt1);
        float cr0 = __expf(mr0 - mn0), cr1 = __expf(mr1 - mn1);
        mr0 = mn0; mr1 = mn1;

        float rs0 = 0.f, rs1 = 0.f;
        float* p0row = &sQP[(m0 + g) * AQ_STR + 2 * t];
        float* p1row = &sQP[(m0 + 8 + g) * AQ_STR + 2 * t];
#pragma unroll
        for (int nt = 0; nt < 8; nt++) {
            float e0 = __expf(s[nt][0] - mn0);
            float e1 = __expf(s[nt][1] - mn0);
            float e2 = __expf(s[nt][2] - mn1);
            float e3 = __expf(s[nt][3] - mn1);
            rs0 += e0 + e1;
            rs1 += e2 + e3;
            p0row[nt * 8 + 0] = tf32r(e0);
            p0row[nt * 8 + 1] = tf32r(e1);
            p1row[nt * 8 + 0] = tf32r(e2);
            p1row[nt * 8 + 1] = tf32r(e3);
        }
        rs0 += __shfl_xor_sync(0xffffffffu, rs0, 1);
        rs0 += __shfl_xor_sync(0xffffffffu, rs0, 2);
        rs1 += __shfl_xor_sync(0xffffffffu, rs1, 1);
        rs1 += __shfl_xor_sync(0xffffffffu, rs1, 2);
        l0 = l0 * cr0 + rs0;
        l1 = l1 * cr1 + rs1;

#pragma unroll
        for (int nt = 0; nt < 8; nt++) {
            o[nt][0] *= cr0; o[nt][1] *= cr0;
            o[nt][2] *= cr1; o[nt][3] *= cr1;
        }
        __syncwarp();  // P stores visible to all lanes of this warp

        // O += P @ V
#pragma unroll
        for (int ks = 0; ks < 8; ks++) {
            const int kk = ks * 8;
            uint32_t ap[4];
            ap[0] = __float_as_uint(sQP[(m0 + g) * AQ_STR + kk + t]);
            ap[1] = __float_as_uint(sQP[(m0 + 8 + g) * AQ_STR + kk + t]);
            ap[2] = __float_as_uint(sQP[(m0 + g) * AQ_STR + kk + t + 4]);
            ap[3] = __float_as_uint(sQP[(m0 + 8 + g) * AQ_STR + kk + t + 4]);
#pragma unroll
            for (int nt = 0; nt < 8; nt++) {
                uint32_t bf[2];
                bf[0] = __float_as_uint(sV[(kk + t) * AV_STR + nt * 8 + g]);
                bf[1] = __float_as_uint(sV[(kk + t + 4) * AV_STR + nt * 8 + g]);
                mma_tf32(o[nt], ap, bf);
            }
        }
        __syncwarp();  // P reads done before next iter's P stores
    }

    // Epilogue: normalize and write (B*L, D)
    float inv0 = 1.0f / l0, inv1 = 1.0f / l1;
    float* ob0 = out + (size_t)(b * LSEQ + row0g) * DMODEL + h * HDIM + 2 * t;
    float* ob1 = out + (size_t)(b * LSEQ + row1g) * DMODEL + h * HDIM + 2 * t;
#pragma unroll
    for (int nt = 0; nt < 8; nt++) {
        *reinterpret_cast<float2*>(ob0 + nt * 8) =
            make_float2(o[nt][0] * inv0, o[nt][1] * inv0);
        *reinterpret_cast<float2*>(ob1 + nt * 8) =
            make_float2(o[nt][2] * inv1, o[nt][3] * inv1);
    }
}

// ---------------------------------------------------------------------------
extern "C" void kernel_launch(void* const* d_in, const int* in_sizes, int n_in,
                              void* d_out, int out_size)
{
    (void)in_sizes; (void)n_in; (void)out_size;
    const float* x      = (const float*)d_in[0];
    // d_in[1] = attn_mask (always causal triu(k=1); implemented directly)
    const float* w_qkv  = (const float*)d_in[2];
    const float* w_proj = (const float*)d_in[3];
    const float* b_proj = (const float*)d_in[4];
    float* out = (float*)d_out;

    float* qkv_p = nullptr;
    float* attn_p = nullptr;
    cudaGetSymbolAddress((void**)&qkv_p, g_qkv);
    cudaGetSymbolAddress((void**)&attn_p, g_attn);

    const int smem_bytes = ATTN_SMEM_FLOATS * (int)sizeof(float);
    cudaFuncSetAttribute(attn_mma_kernel,
                         cudaFuncAttributeMaxDynamicSharedMemorySize,
                         smem_bytes);

    // 1) QKV GEMM: (8192,1024) @ (1024,3072)  [tf32 tensor cores]
    {
        dim3 grid(QKVN / GBN, MROWS / GBM);
        gemm_tf32_kernel<<<grid, 256>>>(x, w_qkv, qkv_p, MROWS, QKVN, DMODEL,
                                        nullptr);
    }
    // 2) Causal flash attention [tf32 tensor cores]
    {
        dim3 grid(LSEQ / BLKQ, BB * NH);
        attn_mma_kernel<<<grid, 256, smem_bytes>>>(qkv_p, attn_p);
    }
    // 3) Output projection + bias: (8192,1024) @ (1024,1024) [tf32]
    {
        dim3 grid(DMODEL / GBN, MROWS / GBM);
        gemm_tf32_kernel<<<grid, 256>>>(attn_p, w_proj, out, MROWS, DMODEL,
                                        DMODEL, b_proj);
    }
}